// round 2
// baseline (speedup 1.0000x reference)
#include <cuda_runtime.h>
#include <cuda_bf16.h>
#include <math.h>

// inputs (metadata order): x[f32 N_NODES*128] (unused), src[i32 E], dst[i32 E],
// path_len[i32 E], b[f32 5]. output: f32 N_NODES*N_NODES.
//
// Semantics: out = zeros; out[src[i], dst[i]] = b[min(path_len[i],5)-1], with
// LAST duplicate (highest i) winning.
//
// 3 phases per replay:
//   1) memset out to 0 (baseline for atomicMax + final zeros for untouched cells)
//   2) pass A: atomicMax(out_i[pos], ((i+1)<<3)|idx)  -- unique keys, max == last i
//   3) pass B: pair i re-reads its cell; the unique winner (v>>3 == i+1)
//      stores b[v&7]. Only ~E scattered sectors touched, no full-matrix sweep.

#ifndef MAX_PATH_DISTANCE
#define MAX_PATH_DISTANCE 5
#endif

__device__ __forceinline__ int pack_key(int pair_idx, int plen) {
    int idx = min(plen, MAX_PATH_DISTANCE) - 1;   // 0..4
    return ((pair_idx + 1) << 3) | idx;           // > 0, fits in 31 bits
}

__global__ void scatter_max_kernel(const int* __restrict__ src,
                                   const int* __restrict__ dst,
                                   const int* __restrict__ plen,
                                   int* __restrict__ out_i,
                                   int n_pairs, int n_nodes) {
    int t = blockIdx.x * blockDim.x + threadIdx.x;
    int base = t * 4;
    if (base >= n_pairs) return;

    if (base + 3 < n_pairs) {
        int4 s = *reinterpret_cast<const int4*>(src + base);
        int4 d = *reinterpret_cast<const int4*>(dst + base);
        int4 p = *reinterpret_cast<const int4*>(plen + base);

        long long p0 = (long long)s.x * n_nodes + d.x;
        long long p1 = (long long)s.y * n_nodes + d.y;
        long long p2 = (long long)s.z * n_nodes + d.z;
        long long p3 = (long long)s.w * n_nodes + d.w;

        atomicMax(out_i + p0, pack_key(base + 0, p.x));
        atomicMax(out_i + p1, pack_key(base + 1, p.y));
        atomicMax(out_i + p2, pack_key(base + 2, p.z));
        atomicMax(out_i + p3, pack_key(base + 3, p.w));
    } else {
        for (int k = base; k < n_pairs; ++k) {
            long long pos = (long long)src[k] * n_nodes + dst[k];
            atomicMax(out_i + pos, pack_key(k, plen[k]));
        }
    }
}

__global__ void winner_write_kernel(const int* __restrict__ src,
                                    const int* __restrict__ dst,
                                    int* __restrict__ out_i,
                                    const float* __restrict__ b,
                                    int n_pairs, int n_nodes) {
    int t = blockIdx.x * blockDim.x + threadIdx.x;
    int base = t * 4;
    if (base >= n_pairs) return;

    float* out_f = reinterpret_cast<float*>(out_i);

    if (base + 3 < n_pairs) {
        int4 s = *reinterpret_cast<const int4*>(src + base);
        int4 d = *reinterpret_cast<const int4*>(dst + base);

        long long p0 = (long long)s.x * n_nodes + d.x;
        long long p1 = (long long)s.y * n_nodes + d.y;
        long long p2 = (long long)s.z * n_nodes + d.z;
        long long p3 = (long long)s.w * n_nodes + d.w;

        int v0 = out_i[p0];
        int v1 = out_i[p1];
        int v2 = out_i[p2];
        int v3 = out_i[p3];

        if (((unsigned)v0 >> 3) == (unsigned)(base + 1)) out_f[p0] = __ldg(&b[v0 & 7]);
        if (((unsigned)v1 >> 3) == (unsigned)(base + 2)) out_f[p1] = __ldg(&b[v1 & 7]);
        if (((unsigned)v2 >> 3) == (unsigned)(base + 3)) out_f[p2] = __ldg(&b[v2 & 7]);
        if (((unsigned)v3 >> 3) == (unsigned)(base + 4)) out_f[p3] = __ldg(&b[v3 & 7]);
    } else {
        for (int k = base; k < n_pairs; ++k) {
            long long pos = (long long)src[k] * n_nodes + dst[k];
            int v = out_i[pos];
            if (((unsigned)v >> 3) == (unsigned)(k + 1)) out_f[pos] = __ldg(&b[v & 7]);
        }
    }
}

extern "C" void kernel_launch(void* const* d_in, const int* in_sizes, int n_in,
                              void* d_out, int out_size) {
    const int* src  = (const int*)d_in[1];
    const int* dst  = (const int*)d_in[2];
    const int* plen = (const int*)d_in[3];
    const float* b  = (const float*)d_in[4];

    int n_pairs = in_sizes[1];
    int n_nodes = (int)llround(sqrt((double)out_size));

    int* out_i = (int*)d_out;

    // 1) zero baseline
    cudaMemsetAsync(d_out, 0, (size_t)out_size * sizeof(float));

    int threads = 256;
    int work = (n_pairs + 3) / 4;
    int blocks = (work + threads - 1) / threads;

    // 2) deterministic last-write-wins scatter via packed atomicMax
    scatter_max_kernel<<<blocks, threads>>>(src, dst, plen, out_i,
                                            n_pairs, n_nodes);

    // 3) winners overwrite their cells with the real float value
    winner_write_kernel<<<blocks, threads>>>(src, dst, out_i, b,
                                             n_pairs, n_nodes);
}

// round 4
// speedup vs baseline: 1.5836x; 1.5836x over previous
#include <cuda_runtime.h>
#include <cuda_bf16.h>
#include <math.h>

// inputs (metadata order): x[f32] (unused), src[i32 E], dst[i32 E],
// path_len[i32 E], b[f32 5]. output: f32 N_NODES*N_NODES.
//
// out = zeros; out[src[i], dst[i]] = b[min(path_len[i],5)-1], LAST dup wins.
//
// No memset. Keys live in NaN-payload space: key = KEY_BASE + i with
// KEY_BASE = 0x7F800001. As signed ints, every key is greater than any finite
// float bit pattern (max finite = 0x7F7FFFFF) and any negative float / the
// harness 0xAA poison (negative). So atomicMax over whatever d_out currently
// holds is correct with zero initialization work, for ANY prior contents that
// are finite floats or poison.
//
//   Pass A: atomicMax(out_i[src*n+dst], KEY_BASE + i)      (last i wins)
//   Pass B: full int4 sweep; v >= KEY_BASE -> gather plen[v-KEY_BASE],
//           write b[min(plen,5)-1]; v == 0 -> already correct, skip store;
//           otherwise write 0.

#ifndef MAX_PATH_DISTANCE
#define MAX_PATH_DISTANCE 5
#endif

#define KEY_BASE 0x7F800001

__global__ void scatter_max_kernel(const int* __restrict__ src,
                                   const int* __restrict__ dst,
                                   int* __restrict__ out_i,
                                   int n_pairs, int n_nodes) {
    int t = blockIdx.x * blockDim.x + threadIdx.x;
    int base = t * 4;
    if (base >= n_pairs) return;

    if (base + 3 < n_pairs) {
        int4 s = *reinterpret_cast<const int4*>(src + base);
        int4 d = *reinterpret_cast<const int4*>(dst + base);

        long long p0 = (long long)s.x * n_nodes + d.x;
        long long p1 = (long long)s.y * n_nodes + d.y;
        long long p2 = (long long)s.z * n_nodes + d.z;
        long long p3 = (long long)s.w * n_nodes + d.w;

        atomicMax(out_i + p0, KEY_BASE + base + 0);
        atomicMax(out_i + p1, KEY_BASE + base + 1);
        atomicMax(out_i + p2, KEY_BASE + base + 2);
        atomicMax(out_i + p3, KEY_BASE + base + 3);
    } else {
        for (int k = base; k < n_pairs; ++k) {
            long long pos = (long long)src[k] * n_nodes + dst[k];
            atomicMax(out_i + pos, KEY_BASE + k);
        }
    }
}

__device__ __forceinline__ float decode_one(int v, const int* __restrict__ plen,
                                            const float* __restrict__ b) {
    if (v >= KEY_BASE) {
        int i = v - KEY_BASE;
        int p = __ldg(&plen[i]);
        int idx = min(p, MAX_PATH_DISTANCE) - 1;
        return __ldg(&b[idx]);
    }
    return 0.0f;
}

__global__ void decode_kernel(int* __restrict__ out_i,
                              const int* __restrict__ plen,
                              const float* __restrict__ b,
                              int total4) {
    int i = blockIdx.x * blockDim.x + threadIdx.x;
    if (i >= total4) return;
    int4 v = reinterpret_cast<const int4*>(out_i)[i];

    // Fast path: all four cells read 0 -> all four correct values are 0
    // (a zero cell is by construction untouched by this replay's pass A).
    if ((v.x | v.y | v.z | v.w) == 0) return;

    float4 r;
    r.x = decode_one(v.x, plen, b);
    r.y = decode_one(v.y, plen, b);
    r.z = decode_one(v.z, plen, b);
    r.w = decode_one(v.w, plen, b);
    reinterpret_cast<float4*>(out_i)[i] = r;
}

extern "C" void kernel_launch(void* const* d_in, const int* in_sizes, int n_in,
                              void* d_out, int out_size) {
    const int* src  = (const int*)d_in[1];
    const int* dst  = (const int*)d_in[2];
    const int* plen = (const int*)d_in[3];
    const float* b  = (const float*)d_in[4];

    int n_pairs = in_sizes[1];
    int n_nodes = (int)llround(sqrt((double)out_size));

    int* out_i = (int*)d_out;

    // Pass A: deterministic last-write-wins scatter via NaN-space atomicMax
    {
        int threads = 256;
        int work = (n_pairs + 3) / 4;
        int blocks = (work + threads - 1) / threads;
        scatter_max_kernel<<<blocks, threads>>>(src, dst, out_i,
                                                n_pairs, n_nodes);
    }

    // Pass B: full sweep decode (keys -> b values, everything else -> 0,
    // stores skipped where the cell already holds the correct 0)
    {
        int total4 = out_size / 4;
        int threads = 256;
        int blocks = (total4 + threads - 1) / threads;
        decode_kernel<<<blocks, threads>>>(out_i, plen, b, total4);
    }
}